// round 14
// baseline (speedup 1.0000x reference)
#include <cuda_runtime.h>
#include <cstdint>

#define N0 6144
#define DD 320
#define N1 4915
#define N2 2949
#define NNZ_MAX 1900000
#define SORT_N 8192
#define CH 128            // columns per SpMM stage chunk
#define NCH 48            // 6144/128

// ---------------- scratch (__device__ globals; no allocations) ----------------
__device__ __align__(16) float g_h[N0 * DD];
__device__ __align__(16) float g_T[N0 * DD];
__device__ __align__(16) float g_Tg[N0 * DD];
__device__ __align__(16) float g_u[N0 * DD];
__device__ __align__(16) float g_v[N0 * DD];
__device__ __align__(16) float g_Xstart[N0 * DD];
__device__ __align__(16) float g_Xfin[N0 * DD];
__device__ __align__(16) float g_down0[N0 * DD];
__device__ __align__(16) float g_down1[N1 * DD];
__device__ __align__(16) float g_egc[N0 * DD];
__device__ float g_es[N0];
__device__ float g_ed[N0];
__device__ float g_sc[N0];
__device__ unsigned long long g_keys[SORT_N];
__device__ int g_rowcnt[N0];
__device__ int g_rowptr[N0 + 1];
__device__ int g_col[NNZ_MAX];
__device__ int g_rcp[N0 * (NCH + 1)];   // per-row CSR offset at each 128-col chunk
__device__ int g_idxs[N1];
__device__ int g_gidx1[N1];
__device__ int g_map1[N0];
__device__ int g_gidx2[N2];
__device__ int g_map2[N0];
__device__ int g_gidx1f[N1];
__device__ int g_map1f[N0];
__device__ int g_idx1f[N2];
__device__ int g_imap1f[N1];

// ---------------- CSR build ----------------
__global__ void k_count(const float* __restrict__ A, int* __restrict__ rowcnt) {
    int i = blockIdx.x;
    int c = 0;
    const float* row = A + (size_t)i * N0;
    for (int j = threadIdx.x; j < N0; j += 256) c += (row[j] > 0.f);
    __shared__ int sh[256];
    sh[threadIdx.x] = c; __syncthreads();
    for (int s = 128; s > 0; s >>= 1) {
        if (threadIdx.x < s) sh[threadIdx.x] += sh[threadIdx.x + s];
        __syncthreads();
    }
    if (threadIdx.x == 0) rowcnt[i] = sh[0];
}

__global__ void k_scan(const int* __restrict__ rowcnt, int* __restrict__ rowptr) {
    __shared__ int part[1024];
    int t = threadIdx.x;
    int base = t * 6;
    int loc[6]; int s = 0;
    for (int q = 0; q < 6; q++) { loc[q] = s; s += rowcnt[base + q]; }
    part[t] = s; __syncthreads();
    for (int off = 1; off < 1024; off <<= 1) {
        int v = (t >= off) ? part[t - off] : 0;
        __syncthreads();
        part[t] += v;
        __syncthreads();
    }
    int excl = (t == 0) ? 0 : part[t - 1];
    for (int q = 0; q < 6; q++) rowptr[base + q] = excl + loc[q];
    if (t == 1023) rowptr[N0] = part[1023];
}

__global__ void k_fill(const float* __restrict__ A, const int* __restrict__ rowptr,
                       int* __restrict__ col) {
    int i = blockIdx.x;
    int t = threadIdx.x;
    __shared__ int cnt[256];
    const float* row = A + (size_t)i * N0;
    int c0 = t * 24;
    int c = 0;
    for (int q = 0; q < 24; q++) c += (row[c0 + q] > 0.f);
    cnt[t] = c; __syncthreads();
    for (int off = 1; off < 256; off <<= 1) {
        int v = (t >= off) ? cnt[t - off] : 0;
        __syncthreads();
        cnt[t] += v;
        __syncthreads();
    }
    int pos = rowptr[i] + ((t == 0) ? 0 : cnt[t - 1]);
    for (int q = 0; q < 24; q++)
        if (row[c0 + q] > 0.f) col[pos++] = c0 + q;
}

// rcp[i][c] = CSR index of first edge of row i with col >= c*128 (binary search)
__global__ void k_rcp(const int* __restrict__ rowptr, const int* __restrict__ col,
                      int* __restrict__ rcp) {
    int i = blockIdx.x;
    int c = threadIdx.x;         // 0..NCH
    if (c == NCH) { rcp[i * (NCH + 1) + NCH] = rowptr[i + 1]; return; }
    int lo = rowptr[i], hi = rowptr[i + 1];
    int bound = c * CH;
    while (lo < hi) {
        int mid = (lo + hi) >> 1;
        if (col[mid] < bound) lo = mid + 1; else hi = mid;
    }
    rcp[i * (NCH + 1) + c] = lo;
}

// ---------- dense GEMM: C = A[MxKK] @ B[KKxNC] (+bias)(+res); 128x64 tile ----------
template <int KK, int NC>
__global__ void __launch_bounds__(256) k_gemm(
        const float* __restrict__ A, const float* __restrict__ B,
        const float* __restrict__ bias, const float* __restrict__ res,
        float* __restrict__ C, int M) {
    __shared__ __align__(16) float As[2][8][136];
    __shared__ __align__(16) float Bs[2][8][64];
    int tid = threadIdx.x;
    int row0 = blockIdx.x * 128, col0 = blockIdx.y * 64;
    int ar = tid >> 1, ac = (tid & 1) * 4;
    int br = tid >> 5, bc = (tid & 31) * 2;
    int ty = tid >> 4, tx = tid & 15;
    float acc[8][4] = {};
    constexpr int nk = KK >> 3;
    float4 aReg; float2 bReg;
    {
        int r = row0 + ar;
        aReg = (r < M) ? *(const float4*)&A[(size_t)r * KK + ac]
                       : make_float4(0.f, 0.f, 0.f, 0.f);
        bReg = *(const float2*)&B[(size_t)br * NC + col0 + bc];
        As[0][ac + 0][ar] = aReg.x; As[0][ac + 1][ar] = aReg.y;
        As[0][ac + 2][ar] = aReg.z; As[0][ac + 3][ar] = aReg.w;
        Bs[0][br][bc] = bReg.x; Bs[0][br][bc + 1] = bReg.y;
    }
    __syncthreads();
    int nb = 0;
    #pragma unroll 1
    for (int kt = 0; kt < nk; kt++) {
        if (kt + 1 < nk) {
            int kk = (kt + 1) << 3;
            int r = row0 + ar;
            aReg = (r < M) ? *(const float4*)&A[(size_t)r * KK + kk + ac]
                           : make_float4(0.f, 0.f, 0.f, 0.f);
            bReg = *(const float2*)&B[(size_t)(kk + br) * NC + col0 + bc];
        }
        #pragma unroll
        for (int k = 0; k < 8; k++) {
            float4 a0 = *(const float4*)&As[nb][k][ty * 8];
            float4 a1 = *(const float4*)&As[nb][k][ty * 8 + 4];
            float4 b  = *(const float4*)&Bs[nb][k][tx * 4];
            float av[8] = {a0.x, a0.y, a0.z, a0.w, a1.x, a1.y, a1.z, a1.w};
            #pragma unroll
            for (int i = 0; i < 8; i++) {
                acc[i][0] += av[i] * b.x; acc[i][1] += av[i] * b.y;
                acc[i][2] += av[i] * b.z; acc[i][3] += av[i] * b.w;
            }
        }
        if (kt + 1 < nk) {
            int o = nb ^ 1;
            As[o][ac + 0][ar] = aReg.x; As[o][ac + 1][ar] = aReg.y;
            As[o][ac + 2][ar] = aReg.z; As[o][ac + 3][ar] = aReg.w;
            Bs[o][br][bc] = bReg.x; Bs[o][br][bc + 1] = bReg.y;
            __syncthreads();
            nb = o;
        }
    }
    #pragma unroll
    for (int i = 0; i < 8; i++) {
        int r = row0 + ty * 8 + i;
        if (r < M) {
            #pragma unroll
            for (int j = 0; j < 4; j++) {
                int c = col0 + tx * 4 + j;
                float v = acc[i][j];
                if (bias) v += bias[c];
                if (res)  v += res[(size_t)r * NC + c];
                C[(size_t)r * NC + c] = v;
            }
        }
    }
}

// ---- tiled SpMM over GLOBAL rows: SMEM-staged columns, register accumulators ----
// block = (row-tile of 128 global rows) x (64 feature cols). 48 chunks of 128 cols.
// Staged value for dropped columns is 0.0f: x+0.0f is exact, so per-row summation
// order/rounding is IDENTICAL to the CSR-order gather (ascending j).
__global__ void __launch_bounds__(256) k_spmm2(
        const int* __restrict__ rcp, const int* __restrict__ col,
        const int* __restrict__ map, const int* __restrict__ imap,
        const float* __restrict__ Xin, float* __restrict__ Xout) {
    __shared__ __align__(16) float Xs[CH][64];
    __shared__ int sl[CH];
    int tid = threadIdx.x;
    int row0 = blockIdx.x * 128;
    int c0 = blockIdx.y * 64;
    int w = tid >> 5, lane = tid & 31;
    float2 acc[16];
    #pragma unroll
    for (int r = 0; r < 16; r++) acc[r] = make_float2(0.f, 0.f);

    for (int ch = 0; ch < NCH; ch++) {
        __syncthreads();   // previous compute done before restaging
        if (tid < CH) {
            int j = ch * CH + tid;
            int l = map ? map[j] : j;
            if (imap && l >= 0) l = imap[l];
            sl[tid] = l;
        }
        __syncthreads();
        #pragma unroll
        for (int k = 0; k < 8; k++) {
            int idx = tid + k * 256;       // 0..2047 float4 slots
            int r = idx >> 4, q = idx & 15;
            int l = sl[r];
            float4 v = (l >= 0) ? *(const float4*)&Xin[(size_t)l * DD + c0 + q * 4]
                                : make_float4(0.f, 0.f, 0.f, 0.f);
            *(float4*)&Xs[r][q * 4] = v;
        }
        __syncthreads();
        int rbase = (row0 + w * 16) * (NCH + 1) + ch;
        #pragma unroll
        for (int rr = 0; rr < 16; rr++) {
            int p = rcp[rbase + rr * (NCH + 1)];
            int e = rcp[rbase + rr * (NCH + 1) + 1];
            #pragma unroll 2
            for (; p < e; p++) {
                int jl = col[p] & (CH - 1);
                float2 x = *(const float2*)&Xs[jl][lane * 2];
                acc[rr].x += x.x; acc[rr].y += x.y;
            }
        }
    }
    #pragma unroll
    for (int rr = 0; rr < 16; rr++) {
        int i = row0 + w * 16 + rr;
        *(float2*)&Xout[(size_t)i * DD + c0 + lane * 2] = acc[rr];
    }
}

// dst[i] = src[gidx[i]]  (compact pooled rows out of the global-row SpMM result)
__global__ void k_rowgather(const float* __restrict__ src, const int* __restrict__ gidx,
                            float* __restrict__ dst, int n) {
    int i = blockIdx.x;
    int t = threadIdx.x;
    dst[(size_t)i * DD + t] = src[(size_t)gidx[i] * DD + t];
}

// ---- fused GAT: online-softmax edge scan + weighted fp32 gather + elu ----
// Gather stays fp32 — feature magnitudes reach ~3e6 in pass 2 (fp16 overflows,
// bf16/fp16-with-scale erode accuracy toward the 1e-3 threshold).
__global__ void k_gat(const int* __restrict__ rowptr, const int* __restrict__ col,
                      const int* __restrict__ gidx, const int* __restrict__ map,
                      const float* __restrict__ h, const float* __restrict__ es,
                      const float* __restrict__ ed, float* __restrict__ out, int n) {
    int i = blockIdx.x;
    int t = threadIdx.x;  // 320
    int g = gidx ? gidx[i] : i;
    int s0 = rowptr[g], e0 = rowptr[g + 1];
    float esi = es[i];
    __shared__ float rm[10], rs[10];
    __shared__ float smax, sinv;
    __shared__ int sj[512];
    __shared__ float sw[512];

    float m = -3e38f, sv = 0.f;
    for (int q = s0 + t; q < e0; q += 320) {
        int c = col[q];
        int l = map ? map[c] : c;
        if (l >= 0) {
            float v = esi + ed[l];
            v = v > 0.f ? v : 0.2f * v;
            if (v > m) { sv = sv * expf(m - v) + 1.f; m = v; }
            else sv += expf(v - m);
        }
    }
    for (int o = 16; o; o >>= 1) {
        float mo = __shfl_xor_sync(0xffffffffu, m, o);
        float so = __shfl_xor_sync(0xffffffffu, sv, o);
        float M2 = fmaxf(m, mo);
        sv = sv * expf(m - M2) + so * expf(mo - M2);
        m = M2;
    }
    if ((t & 31) == 0) { rm[t >> 5] = m; rs[t >> 5] = sv; }
    __syncthreads();
    if (t == 0) {
        float M2 = rm[0], S = rs[0];
        for (int q = 1; q < 10; q++) {
            float Mn = fmaxf(M2, rm[q]);
            S = S * expf(M2 - Mn) + rs[q] * expf(rm[q] - Mn);
            M2 = Mn;
        }
        smax = M2; sinv = 1.f / S;
    }
    __syncthreads();
    float M = smax, inv = sinv;

    float acc = 0.f;
    for (int base = s0; base < e0; base += 512) {
        int cnt = min(512, e0 - base);
        __syncthreads();
        for (int q = t; q < cnt; q += 320) {
            int c = col[base + q];
            int l = map ? map[c] : c;
            sj[q] = l;
            if (l >= 0) {
                float v = esi + ed[l];
                v = v > 0.f ? v : 0.2f * v;
                sw[q] = expf(v - M);
            } else sw[q] = 0.f;
        }
        __syncthreads();
        #pragma unroll 4
        for (int q = 0; q < cnt; q++) {
            int l = sj[q];
            if (l >= 0) acc += sw[q] * h[(size_t)l * DD + t];
        }
    }
    float x = acc * inv;
    out[(size_t)i * DD + t] = x > 0.f ? x : expf(x) - 1.f;
}

// ---------------- small vector kernels ----------------
__global__ void k_attn_vec(const float* __restrict__ h, const float* __restrict__ a,
                           float* __restrict__ es, float* __restrict__ ed, int n) {
    int w = threadIdx.x >> 5, lane = threadIdx.x & 31;
    int row = blockIdx.x * 4 + w;
    if (row >= n) return;
    float s1 = 0.f, s2 = 0.f;
    for (int j = lane; j < DD; j += 32) {
        float hv = h[(size_t)row * DD + j];
        s1 += hv * a[j];
        s2 += hv * a[DD + j];
    }
    for (int o = 16; o; o >>= 1) {
        s1 += __shfl_xor_sync(0xffffffffu, s1, o);
        s2 += __shfl_xor_sync(0xffffffffu, s2, o);
    }
    if (lane == 0) { es[row] = s1; ed[row] = s2; }
}

__global__ void k_scores(const float* __restrict__ X, const float* __restrict__ w,
                         const float* __restrict__ bptr, int bidx,
                         float* __restrict__ sc, int n) {
    int wi = threadIdx.x >> 5, lane = threadIdx.x & 31;
    int row = blockIdx.x * 4 + wi;
    if (row >= n) return;
    float s = 0.f;
    for (int j = lane; j < DD; j += 32) s += X[(size_t)row * DD + j] * w[j];
    for (int o = 16; o; o >>= 1) s += __shfl_xor_sync(0xffffffffu, s, o);
    if (lane == 0) {
        float x = (s + bptr[bidx]) * 0.01f;
        sc[row] = 1.f / (1.f + expf(-x));
    }
}

// ---- SMEM bitonic sort of SORT_N keys; writes top knum keys ----
__global__ void k_sort(const float* __restrict__ sc, int n,
                       unsigned long long* __restrict__ keys_out, int knum) {
    extern __shared__ unsigned long long skeys[];
    int t = threadIdx.x;  // 1024
    for (int i = t; i < SORT_N; i += 1024) {
        unsigned long long kv = ~0ull;
        if (i < n) {
            unsigned int u = __float_as_uint(sc[i]);
            unsigned int ord = (u >> 31) ? ~u : (u | 0x80000000u);
            kv = ((unsigned long long)(~ord) << 32) | (unsigned int)i;
        }
        skeys[i] = kv;
    }
    __syncthreads();
    for (int kk = 2; kk <= SORT_N; kk <<= 1) {
        for (int j = kk >> 1; j > 0; j >>= 1) {
            #pragma unroll 4
            for (int tt = t; tt < SORT_N / 2; tt += 1024) {
                int i = ((tt & ~(j - 1)) << 1) | (tt & (j - 1));
                int l = i + j;
                bool asc = ((i & kk) == 0);
                unsigned long long a = skeys[i], b = skeys[l];
                if ((a > b) == asc) { skeys[i] = b; skeys[l] = a; }
            }
            __syncthreads();
        }
    }
    for (int i = t; i < knum; i += 1024) keys_out[i] = skeys[i];
}

__global__ void k_pool(const unsigned long long* __restrict__ keys, const float* __restrict__ sc,
                       const float* __restrict__ Xin, const int* __restrict__ gidx_in,
                       float* __restrict__ Xout, int* __restrict__ idx_loc,
                       int* __restrict__ gidx_out, int knum) {
    int i = blockIdx.x;
    int t = threadIdx.x;
    int li = (int)(keys[i] & 0xffffffffull);
    float v = sc[li];
    Xout[(size_t)i * DD + t] = Xin[(size_t)li * DD + t] * v;
    if (t == 0) {
        idx_loc[i] = li;
        gidx_out[i] = gidx_in ? gidx_in[li] : li;
    }
}

__global__ void k_seti(int* __restrict__ p, int v, int n) {
    int i = blockIdx.x * 256 + threadIdx.x;
    if (i < n) p[i] = v;
}
__global__ void k_map_set(const int* __restrict__ src, int* __restrict__ map, int kn) {
    int i = blockIdx.x * 256 + threadIdx.x;
    if (i < kn) map[src[i]] = i;
}
__global__ void k_copyf(float* __restrict__ dst, const float* __restrict__ src, int n) {
    int i = blockIdx.x * 256 + threadIdx.x;
    for (; i < n; i += gridDim.x * 256) dst[i] = src[i];
}

// ---------------- host orchestration ----------------
static void gemm(const float* A, const float* B, const float* bias, const float* res,
                 float* C, int M) {
    dim3 grid((M + 127) / 128, 320 / 64);
    k_gemm<320, 320><<<grid, 256>>>(A, B, bias, res, C, M);
}

static void spmm2(const int* rcp, const int* colv, const int* map, const int* imap,
                  const float* Xin, float* Xout) {
    dim3 grid(NCH, DD / 64);   // 48 row-tiles x 5 feature-tiles
    k_spmm2<<<grid, 256>>>(rcp, colv, map, imap, Xin, Xout);
}

template <typename T>
static T* sym_addr(const void* symbol) {
    void* p = nullptr;
    cudaGetSymbolAddress(&p, symbol);
    return (T*)p;
}

extern "C" void kernel_launch(void* const* d_in, const int* in_sizes, int n_in,
                              void* d_out, int out_size) {
    const float* A      = (const float*)d_in[0];
    const float* X      = (const float*)d_in[1];
    const float* sg_W   = (const float*)d_in[2];
    const float* sg_a   = (const float*)d_in[3];
    const float* bg_W   = (const float*)d_in[4];
    const float* bg_a   = (const float*)d_in[5];
    const float* eg_W   = (const float*)d_in[6];
    const float* eg_a   = (const float*)d_in[7];
    const float* down_W = (const float*)d_in[8];
    const float* down_b = (const float*)d_in[9];
    const float* up_W   = (const float*)d_in[10];
    const float* up_b   = (const float*)d_in[11];
    const float* pool_w = (const float*)d_in[12];
    const float* pool_b = (const float*)d_in[13];
    float* outp = (float*)d_out;

    float* p_h      = sym_addr<float>(g_h);
    float* p_T      = sym_addr<float>(g_T);
    float* p_Tg     = sym_addr<float>(g_Tg);
    float* p_u      = sym_addr<float>(g_u);
    float* p_v      = sym_addr<float>(g_v);
    float* p_Xfin   = sym_addr<float>(g_Xfin);
    float* p_down0  = sym_addr<float>(g_down0);
    float* p_down1  = sym_addr<float>(g_down1);
    float* p_egc    = sym_addr<float>(g_egc);
    float* p_es     = sym_addr<float>(g_es);
    float* p_ed     = sym_addr<float>(g_ed);
    float* p_sc     = sym_addr<float>(g_sc);
    unsigned long long* p_keys = sym_addr<unsigned long long>(g_keys);
    int* p_rowcnt = sym_addr<int>(g_rowcnt);
    int* p_rowptr = sym_addr<int>(g_rowptr);
    int* p_col    = sym_addr<int>(g_col);
    int* p_rcp    = sym_addr<int>(g_rcp);
    int* p_idxs   = sym_addr<int>(g_idxs);
    int* p_gidx1  = sym_addr<int>(g_gidx1);
    int* p_map1   = sym_addr<int>(g_map1);
    int* p_gidx2  = sym_addr<int>(g_gidx2);
    int* p_map2   = sym_addr<int>(g_map2);
    int* p_gidx1f = sym_addr<int>(g_gidx1f);
    int* p_map1f  = sym_addr<int>(g_map1f);
    int* p_idx1f  = sym_addr<int>(g_idx1f);
    int* p_imap1f = sym_addr<int>(g_imap1f);

    // start-GAT output doubles as the second half of d_out (the "start" return)
    float* p_Xstart = (out_size >= 2 * N0 * DD) ? (outp + (size_t)N0 * DD)
                                                : sym_addr<float>(g_Xstart);

    cudaFuncSetAttribute(k_sort, cudaFuncAttributeMaxDynamicSharedMemorySize,
                         SORT_N * sizeof(unsigned long long));

    // ---- adjacency: CSR (GAT + rcp) + per-chunk row pointers (tiled SpMM) ----
    k_count<<<N0, 256>>>(A, p_rowcnt);
    k_scan<<<1, 1024>>>(p_rowcnt, p_rowptr);
    k_fill<<<N0, 256>>>(A, p_rowptr, p_col);
    k_rcp<<<N0, NCH + 1>>>(p_rowptr, p_col, p_rcp);

    // ---- start GAT ----
    gemm(X, sg_W, nullptr, nullptr, p_h, N0);
    k_attn_vec<<<(N0 + 3) / 4, 128>>>(p_h, sg_a, p_es, p_ed, N0);
    k_gat<<<N0, 320>>>(p_rowptr, p_col, nullptr, nullptr, p_h, p_es, p_ed, p_Xstart, N0);

    // pass-invariant half of the end-GAT projection: org_X @ eg_W[320:,:]
    gemm(p_Xstart, eg_W + 320 * 320, nullptr, nullptr, p_egc, N0);

    for (int pass = 0; pass < 2; pass++) {
        const float* in0 = (pass == 0) ? p_Xstart : p_Xfin;
        int* gidx1c = (pass == 0) ? p_gidx1f : p_gidx1;
        int* map1c  = (pass == 0) ? p_map1f  : p_map1;
        int* idx1c  = (pass == 0) ? p_idx1f  : p_idxs;
        float* d0 = (pass == 0) ? p_down0 : p_u;
        float* d1 = (pass == 0) ? p_down1 : p_u;

        // down 0 (level 0): global rows == wanted rows, write p_T directly
        spmm2(p_rcp, p_col, nullptr, nullptr, in0, p_T);
        gemm(p_T, down_W, down_b, nullptr, d0, N0);

        // pool 0 (k=0.8): 6144 -> 4915
        k_scores<<<(N0 + 3) / 4, 128>>>(d0, pool_w, pool_b, 0, p_sc, N0);
        k_sort<<<1, 1024, SORT_N * sizeof(unsigned long long)>>>(p_sc, N0, p_keys, N1);
        k_pool<<<N1, 320>>>(p_keys, p_sc, d0, nullptr, p_v, p_idxs, gidx1c, N1);
        k_seti<<<(N0 + 255) / 256, 256>>>(map1c, -1, N0);
        k_map_set<<<(N1 + 255) / 256, 256>>>(gidx1c, map1c, N1);

        // down 1 (level 1): global-row SpMM through map, then compact rows
        spmm2(p_rcp, p_col, map1c, nullptr, p_v, p_Tg);
        k_rowgather<<<N1, 320>>>(p_Tg, gidx1c, p_T, N1);
        gemm(p_T, down_W + 320 * 320, down_b + 320, nullptr, d1, N1);

        // pool 1 (k=0.6): 4915 -> 2949
        k_scores<<<(N1 + 3) / 4, 128>>>(d1, pool_w + 320, pool_b, 1, p_sc, N1);
        k_sort<<<1, 1024, SORT_N * sizeof(unsigned long long)>>>(p_sc, N1, p_keys, N2);
        k_pool<<<N2, 320>>>(p_keys, p_sc, d1, gidx1c, p_v, idx1c, p_gidx2, N2);
        k_seti<<<(N0 + 255) / 256, 256>>>(p_map2, -1, N0);
        k_map_set<<<(N2 + 255) / 256, 256>>>(p_gidx2, p_map2, N2);
        if (pass == 0) {  // inverse of first-pass idx1 (level-1 local -> level-2 local)
            k_seti<<<(N1 + 255) / 256, 256>>>(p_imap1f, -1, N1);
            k_map_set<<<(N2 + 255) / 256, 256>>>(p_idx1f, p_imap1f, N2);
        }

        // bottleneck GAT at level 2
        gemm(p_v, bg_W, nullptr, nullptr, p_h, N2);
        k_attn_vec<<<(N2 + 3) / 4, 128>>>(p_h, bg_a, p_es, p_ed, N2);
        k_gat<<<N2, 320>>>(p_rowptr, p_col, p_gidx2, p_map2, p_h, p_es, p_ed, p_u, N2);

        // up 0: global-row SpMM through map chain, compact rows, GCN + skip
        spmm2(p_rcp, p_col, p_map1f, p_imap1f, p_u, p_Tg);
        k_rowgather<<<N1, 320>>>(p_Tg, p_gidx1f, p_T, N1);
        gemm(p_T, up_W, up_b, p_down1, p_u, N1);

        // up 1: global rows == wanted rows, write p_T directly
        spmm2(p_rcp, p_col, p_map1f, nullptr, p_u, p_T);
        gemm(p_T, up_W + 320 * 320, up_b + 320, p_down0, p_u, N0);

        // end GAT: cat@eg_W = up@eg_W_top + org_X@eg_W_bot (precomputed)
        gemm(p_u, eg_W, nullptr, p_egc, p_h, N0);
        k_attn_vec<<<(N0 + 3) / 4, 128>>>(p_h, eg_a, p_es, p_ed, N0);
        float* outX = (pass == 0) ? p_Xfin : outp;
        k_gat<<<N0, 320>>>(p_rowptr, p_col, nullptr, nullptr, p_h, p_es, p_ed, outX, N0);
    }

    // fallback copy only if start couldn't be written in place
    if (out_size >= 2 * N0 * DD && p_Xstart != outp + (size_t)N0 * DD)
        k_copyf<<<512, 256>>>(outp + (size_t)N0 * DD, p_Xstart, N0 * DD);
}

// round 16
// speedup vs baseline: 2.6006x; 2.6006x over previous
#include <cuda_runtime.h>
#include <cstdint>

#define N0 6144
#define DD 320
#define N1 4915
#define N2 2949
#define NNZ_MAX 1900000
#define SORT_N 8192

// ---------------- scratch (__device__ globals; no allocations) ----------------
__device__ __align__(16) float g_h[N0 * DD];
__device__ __align__(16) float g_T[N0 * DD];
__device__ __align__(16) float g_u[N0 * DD];
__device__ __align__(16) float g_v[N0 * DD];
__device__ __align__(16) float g_Xstart[N0 * DD];
__device__ __align__(16) float g_Xfin[N0 * DD];
__device__ __align__(16) float g_down0[N0 * DD];
__device__ __align__(16) float g_down1[N1 * DD];
__device__ __align__(16) float g_egc[N0 * DD];
__device__ __align__(16) float g_R[N0 * DD];
__device__ __align__(16) float g_FW[DD * DD];
__device__ float g_v1[DD];
__device__ float g_es[N0];
__device__ float g_ed[N0];
__device__ float g_sc[N0];
__device__ unsigned long long g_keys[SORT_N];
__device__ int g_rowcnt[N0];
__device__ int g_rowptr[N0 + 1];
__device__ int g_col[NNZ_MAX];
__device__ int g_idxs[N1];
__device__ int g_gidx1[N1];
__device__ int g_map1[N0];
__device__ int g_gidx2[N2];
__device__ int g_map2[N0];
__device__ int g_gidx1f[N1];
__device__ int g_map1f[N0];
__device__ int g_idx1f[N2];
__device__ int g_imap1f[N1];

// ---------------- CSR build ----------------
__global__ void k_count(const float* __restrict__ A, int* __restrict__ rowcnt) {
    int i = blockIdx.x;
    int c = 0;
    const float* row = A + (size_t)i * N0;
    for (int j = threadIdx.x; j < N0; j += 256) c += (row[j] > 0.f);
    __shared__ int sh[256];
    sh[threadIdx.x] = c; __syncthreads();
    for (int s = 128; s > 0; s >>= 1) {
        if (threadIdx.x < s) sh[threadIdx.x] += sh[threadIdx.x + s];
        __syncthreads();
    }
    if (threadIdx.x == 0) rowcnt[i] = sh[0];
}

__global__ void k_scan(const int* __restrict__ rowcnt, int* __restrict__ rowptr) {
    __shared__ int part[1024];
    int t = threadIdx.x;
    int base = t * 6;
    int loc[6]; int s = 0;
    for (int q = 0; q < 6; q++) { loc[q] = s; s += rowcnt[base + q]; }
    part[t] = s; __syncthreads();
    for (int off = 1; off < 1024; off <<= 1) {
        int v = (t >= off) ? part[t - off] : 0;
        __syncthreads();
        part[t] += v;
        __syncthreads();
    }
    int excl = (t == 0) ? 0 : part[t - 1];
    for (int q = 0; q < 6; q++) rowptr[base + q] = excl + loc[q];
    if (t == 1023) rowptr[N0] = part[1023];
}

__global__ void k_fill(const float* __restrict__ A, const int* __restrict__ rowptr,
                       int* __restrict__ col) {
    int i = blockIdx.x;
    int t = threadIdx.x;
    __shared__ int cnt[256];
    const float* row = A + (size_t)i * N0;
    int c0 = t * 24;
    int c = 0;
    for (int q = 0; q < 24; q++) c += (row[c0 + q] > 0.f);
    cnt[t] = c; __syncthreads();
    for (int off = 1; off < 256; off <<= 1) {
        int v = (t >= off) ? cnt[t - off] : 0;
        __syncthreads();
        cnt[t] += v;
        __syncthreads();
    }
    int pos = rowptr[i] + ((t == 0) ? 0 : cnt[t - 1]);
    for (int q = 0; q < 24; q++)
        if (row[c0 + q] > 0.f) col[pos++] = c0 + q;
}

// ---------- dense GEMM: C = A[MxKK] @ B[KKxNC] (+bias)(+res); 128x64 tile ----------
template <int KK, int NC>
__global__ void __launch_bounds__(256) k_gemm(
        const float* __restrict__ A, const float* __restrict__ B,
        const float* __restrict__ bias, const float* __restrict__ res,
        float* __restrict__ C, int M) {
    __shared__ __align__(16) float As[2][8][136];
    __shared__ __align__(16) float Bs[2][8][64];
    int tid = threadIdx.x;
    int row0 = blockIdx.x * 128, col0 = blockIdx.y * 64;
    int ar = tid >> 1, ac = (tid & 1) * 4;
    int br = tid >> 5, bc = (tid & 31) * 2;
    int ty = tid >> 4, tx = tid & 15;
    float acc[8][4] = {};
    constexpr int nk = KK >> 3;
    float4 aReg; float2 bReg;
    {
        int r = row0 + ar;
        aReg = (r < M) ? *(const float4*)&A[(size_t)r * KK + ac]
                       : make_float4(0.f, 0.f, 0.f, 0.f);
        bReg = *(const float2*)&B[(size_t)br * NC + col0 + bc];
        As[0][ac + 0][ar] = aReg.x; As[0][ac + 1][ar] = aReg.y;
        As[0][ac + 2][ar] = aReg.z; As[0][ac + 3][ar] = aReg.w;
        Bs[0][br][bc] = bReg.x; Bs[0][br][bc + 1] = bReg.y;
    }
    __syncthreads();
    int nb = 0;
    #pragma unroll 1
    for (int kt = 0; kt < nk; kt++) {
        if (kt + 1 < nk) {
            int kk = (kt + 1) << 3;
            int r = row0 + ar;
            aReg = (r < M) ? *(const float4*)&A[(size_t)r * KK + kk + ac]
                           : make_float4(0.f, 0.f, 0.f, 0.f);
            bReg = *(const float2*)&B[(size_t)(kk + br) * NC + col0 + bc];
        }
        #pragma unroll
        for (int k = 0; k < 8; k++) {
            float4 a0 = *(const float4*)&As[nb][k][ty * 8];
            float4 a1 = *(const float4*)&As[nb][k][ty * 8 + 4];
            float4 b  = *(const float4*)&Bs[nb][k][tx * 4];
            float av[8] = {a0.x, a0.y, a0.z, a0.w, a1.x, a1.y, a1.z, a1.w};
            #pragma unroll
            for (int i = 0; i < 8; i++) {
                acc[i][0] += av[i] * b.x; acc[i][1] += av[i] * b.y;
                acc[i][2] += av[i] * b.z; acc[i][3] += av[i] * b.w;
            }
        }
        if (kt + 1 < nk) {
            int o = nb ^ 1;
            As[o][ac + 0][ar] = aReg.x; As[o][ac + 1][ar] = aReg.y;
            As[o][ac + 2][ar] = aReg.z; As[o][ac + 3][ar] = aReg.w;
            Bs[o][br][bc] = bReg.x; Bs[o][br][bc + 1] = bReg.y;
            __syncthreads();
            nb = o;
        }
    }
    #pragma unroll
    for (int i = 0; i < 8; i++) {
        int r = row0 + ty * 8 + i;
        if (r < M) {
            #pragma unroll
            for (int j = 0; j < 4; j++) {
                int c = col0 + tx * 4 + j;
                float v = acc[i][j];
                if (bias) v += bias[c];
                if (res)  v += res[(size_t)r * NC + c];
                C[(size_t)r * NC + c] = v;
            }
        }
    }
}

// small matvec: out[c] = sum_k b[k] * W[k,c]   (one block, DD threads)
__global__ void k_vecmat(const float* __restrict__ b, const float* __restrict__ W,
                         float* __restrict__ out) {
    int c = threadIdx.x;
    float s = 0.f;
    for (int k = 0; k < DD; k++) s += b[k] * W[k * DD + c];
    out[c] = s;
}

// ------- SpMM, CSR gather, float2-vectorized features (160 threads/row) -------
// Per-feature summation order identical to scalar version => bit-identical.
__global__ void k_spmm(const int* __restrict__ rowptr, const int* __restrict__ col,
                       const int* __restrict__ gidx, const int* __restrict__ map,
                       const int* __restrict__ imap,
                       const float* __restrict__ Xin, float* __restrict__ Xout, int n) {
    int i = blockIdx.x;
    int t = threadIdx.x;  // 160
    int g = gidx ? gidx[i] : i;
    int s = rowptr[g], e = rowptr[g + 1];
    __shared__ int sj[512];
    float2 acc = make_float2(0.f, 0.f);
    for (int base = s; base < e; base += 512) {
        int cnt = min(512, e - base);
        __syncthreads();
        for (int q = t; q < cnt; q += 160) {
            int c = col[base + q];
            int l = map ? map[c] : c;
            if (imap && l >= 0) l = imap[l];
            sj[q] = l;
        }
        __syncthreads();
        #pragma unroll 4
        for (int q = 0; q < cnt; q++) {
            int l = sj[q];
            if (l >= 0) {
                float2 x = *(const float2*)&Xin[(size_t)l * DD + 2 * t];
                acc.x += x.x; acc.y += x.y;
            }
        }
    }
    *(float2*)&Xout[(size_t)i * DD + 2 * t] = acc;
}

// ---- fused GAT: online-softmax edge scan + weighted fp32 float2 gather + elu ----
// Gather stays fp32 — feature magnitudes reach ~3e6 in pass 2 (fp16 overflows).
__global__ void k_gat(const int* __restrict__ rowptr, const int* __restrict__ col,
                      const int* __restrict__ gidx, const int* __restrict__ map,
                      const float* __restrict__ h, const float* __restrict__ es,
                      const float* __restrict__ ed, float* __restrict__ out, int n) {
    int i = blockIdx.x;
    int t = threadIdx.x;  // 160 (5 warps)
    int g = gidx ? gidx[i] : i;
    int s0 = rowptr[g], e0 = rowptr[g + 1];
    float esi = es[i];
    __shared__ float rm[5], rs[5];
    __shared__ float smax, sinv;
    __shared__ int sj[512];
    __shared__ float sw[512];

    float m = -3e38f, sv = 0.f;
    for (int q = s0 + t; q < e0; q += 160) {
        int c = col[q];
        int l = map ? map[c] : c;
        if (l >= 0) {
            float v = esi + ed[l];
            v = v > 0.f ? v : 0.2f * v;
            if (v > m) { sv = sv * expf(m - v) + 1.f; m = v; }
            else sv += expf(v - m);
        }
    }
    for (int o = 16; o; o >>= 1) {
        float mo = __shfl_xor_sync(0xffffffffu, m, o);
        float so = __shfl_xor_sync(0xffffffffu, sv, o);
        float M2 = fmaxf(m, mo);
        sv = sv * expf(m - M2) + so * expf(mo - M2);
        m = M2;
    }
    if ((t & 31) == 0) { rm[t >> 5] = m; rs[t >> 5] = sv; }
    __syncthreads();
    if (t == 0) {
        float M2 = rm[0], S = rs[0];
        for (int q = 1; q < 5; q++) {
            float Mn = fmaxf(M2, rm[q]);
            S = S * expf(M2 - Mn) + rs[q] * expf(rm[q] - Mn);
            M2 = Mn;
        }
        smax = M2; sinv = 1.f / S;
    }
    __syncthreads();
    float M = smax, inv = sinv;

    float2 acc = make_float2(0.f, 0.f);
    for (int base = s0; base < e0; base += 512) {
        int cnt = min(512, e0 - base);
        __syncthreads();
        for (int q = t; q < cnt; q += 160) {
            int c = col[base + q];
            int l = map ? map[c] : c;
            sj[q] = l;
            if (l >= 0) {
                float v = esi + ed[l];
                v = v > 0.f ? v : 0.2f * v;
                sw[q] = expf(v - M);
            } else sw[q] = 0.f;
        }
        __syncthreads();
        #pragma unroll 4
        for (int q = 0; q < cnt; q++) {
            int l = sj[q];
            if (l >= 0) {
                float w = sw[q];
                float2 x = *(const float2*)&h[(size_t)l * DD + 2 * t];
                acc.x += w * x.x; acc.y += w * x.y;
            }
        }
    }
    float2 r;
    float x0 = acc.x * inv, x1 = acc.y * inv;
    r.x = x0 > 0.f ? x0 : expf(x0) - 1.f;
    r.y = x1 > 0.f ? x1 : expf(x1) - 1.f;
    *(float2*)&out[(size_t)i * DD + 2 * t] = r;
}

// ---------------- small vector kernels ----------------
__global__ void k_attn_vec(const float* __restrict__ h, const float* __restrict__ a,
                           float* __restrict__ es, float* __restrict__ ed, int n) {
    int w = threadIdx.x >> 5, lane = threadIdx.x & 31;
    int row = blockIdx.x * 4 + w;
    if (row >= n) return;
    float s1 = 0.f, s2 = 0.f;
    for (int j = lane; j < DD; j += 32) {
        float hv = h[(size_t)row * DD + j];
        s1 += hv * a[j];
        s2 += hv * a[DD + j];
    }
    for (int o = 16; o; o >>= 1) {
        s1 += __shfl_xor_sync(0xffffffffu, s1, o);
        s2 += __shfl_xor_sync(0xffffffffu, s2, o);
    }
    if (lane == 0) { es[row] = s1; ed[row] = s2; }
}

__global__ void k_scores(const float* __restrict__ X, const float* __restrict__ w,
                         const float* __restrict__ bptr, int bidx,
                         float* __restrict__ sc, int n) {
    int wi = threadIdx.x >> 5, lane = threadIdx.x & 31;
    int row = blockIdx.x * 4 + wi;
    if (row >= n) return;
    float s = 0.f;
    for (int j = lane; j < DD; j += 32) s += X[(size_t)row * DD + j] * w[j];
    for (int o = 16; o; o >>= 1) s += __shfl_xor_sync(0xffffffffu, s, o);
    if (lane == 0) {
        float x = (s + bptr[bidx]) * 0.01f;
        sc[row] = 1.f / (1.f + expf(-x));
    }
}

// ---- SMEM bitonic sort of SORT_N keys; writes top knum keys ----
__global__ void k_sort(const float* __restrict__ sc, int n,
                       unsigned long long* __restrict__ keys_out, int knum) {
    extern __shared__ unsigned long long skeys[];
    int t = threadIdx.x;  // 1024
    for (int i = t; i < SORT_N; i += 1024) {
        unsigned long long kv = ~0ull;
        if (i < n) {
            unsigned int u = __float_as_uint(sc[i]);
            unsigned int ord = (u >> 31) ? ~u : (u | 0x80000000u);
            kv = ((unsigned long long)(~ord) << 32) | (unsigned int)i;
        }
        skeys[i] = kv;
    }
    __syncthreads();
    for (int kk = 2; kk <= SORT_N; kk <<= 1) {
        for (int j = kk >> 1; j > 0; j >>= 1) {
            #pragma unroll 4
            for (int tt = t; tt < SORT_N / 2; tt += 1024) {
                int i = ((tt & ~(j - 1)) << 1) | (tt & (j - 1));
                int l = i + j;
                bool asc = ((i & kk) == 0);
                unsigned long long a = skeys[i], b = skeys[l];
                if ((a > b) == asc) { skeys[i] = b; skeys[l] = a; }
            }
            __syncthreads();
        }
    }
    for (int i = t; i < knum; i += 1024) keys_out[i] = skeys[i];
}

__global__ void k_pool(const unsigned long long* __restrict__ keys, const float* __restrict__ sc,
                       const float* __restrict__ Xin, const int* __restrict__ gidx_in,
                       float* __restrict__ Xout, int* __restrict__ idx_loc,
                       int* __restrict__ gidx_out, int knum) {
    int i = blockIdx.x;
    int t = threadIdx.x;
    int li = (int)(keys[i] & 0xffffffffull);
    float v = sc[li];
    Xout[(size_t)i * DD + t] = Xin[(size_t)li * DD + t] * v;
    if (t == 0) {
        idx_loc[i] = li;
        gidx_out[i] = gidx_in ? gidx_in[li] : li;
    }
}

__global__ void k_seti(int* __restrict__ p, int v, int n) {
    int i = blockIdx.x * 256 + threadIdx.x;
    if (i < n) p[i] = v;
}
__global__ void k_map_set(const int* __restrict__ src, int* __restrict__ map, int kn) {
    int i = blockIdx.x * 256 + threadIdx.x;
    if (i < kn) map[src[i]] = i;
}
__global__ void k_copyf(float* __restrict__ dst, const float* __restrict__ src, int n) {
    int i = blockIdx.x * 256 + threadIdx.x;
    for (; i < n; i += gridDim.x * 256) dst[i] = src[i];
}

// ---------------- host orchestration ----------------
static void gemm(const float* A, const float* B, const float* bias, const float* res,
                 float* C, int M) {
    dim3 grid((M + 127) / 128, 320 / 64);
    k_gemm<320, 320><<<grid, 256>>>(A, B, bias, res, C, M);
}

template <typename T>
static T* sym_addr(const void* symbol) {
    void* p = nullptr;
    cudaGetSymbolAddress(&p, symbol);
    return (T*)p;
}

extern "C" void kernel_launch(void* const* d_in, const int* in_sizes, int n_in,
                              void* d_out, int out_size) {
    const float* A      = (const float*)d_in[0];
    const float* X      = (const float*)d_in[1];
    const float* sg_W   = (const float*)d_in[2];
    const float* sg_a   = (const float*)d_in[3];
    const float* bg_W   = (const float*)d_in[4];
    const float* bg_a   = (const float*)d_in[5];
    const float* eg_W   = (const float*)d_in[6];
    const float* eg_a   = (const float*)d_in[7];
    const float* down_W = (const float*)d_in[8];
    const float* down_b = (const float*)d_in[9];
    const float* up_W   = (const float*)d_in[10];
    const float* up_b   = (const float*)d_in[11];
    const float* pool_w = (const float*)d_in[12];
    const float* pool_b = (const float*)d_in[13];
    float* outp = (float*)d_out;

    float* p_h      = sym_addr<float>(g_h);
    float* p_T      = sym_addr<float>(g_T);
    float* p_u      = sym_addr<float>(g_u);
    float* p_v      = sym_addr<float>(g_v);
    float* p_Xfin   = sym_addr<float>(g_Xfin);
    float* p_down0  = sym_addr<float>(g_down0);
    float* p_down1  = sym_addr<float>(g_down1);
    float* p_egc    = sym_addr<float>(g_egc);
    float* p_R      = sym_addr<float>(g_R);
    float* p_FW     = sym_addr<float>(g_FW);
    float* p_v1     = sym_addr<float>(g_v1);
    float* p_es     = sym_addr<float>(g_es);
    float* p_ed     = sym_addr<float>(g_ed);
    float* p_sc     = sym_addr<float>(g_sc);
    unsigned long long* p_keys = sym_addr<unsigned long long>(g_keys);
    int* p_rowcnt = sym_addr<int>(g_rowcnt);
    int* p_rowptr = sym_addr<int>(g_rowptr);
    int* p_col    = sym_addr<int>(g_col);
    int* p_idxs   = sym_addr<int>(g_idxs);
    int* p_gidx1  = sym_addr<int>(g_gidx1);
    int* p_map1   = sym_addr<int>(g_map1);
    int* p_gidx2  = sym_addr<int>(g_gidx2);
    int* p_map2   = sym_addr<int>(g_map2);
    int* p_gidx1f = sym_addr<int>(g_gidx1f);
    int* p_map1f  = sym_addr<int>(g_map1f);
    int* p_idx1f  = sym_addr<int>(g_idx1f);
    int* p_imap1f = sym_addr<int>(g_imap1f);

    // start-GAT output doubles as the second half of d_out (the "start" return)
    float* p_Xstart = (out_size >= 2 * N0 * DD) ? (outp + (size_t)N0 * DD)
                                                : sym_addr<float>(g_Xstart);

    cudaFuncSetAttribute(k_sort, cudaFuncAttributeMaxDynamicSharedMemorySize,
                         SORT_N * sizeof(unsigned long long));

    // ---- CSR of A ----
    k_count<<<N0, 256>>>(A, p_rowcnt);
    k_scan<<<1, 1024>>>(p_rowcnt, p_rowptr);
    k_fill<<<N0, 256>>>(A, p_rowptr, p_col);

    // ---- start GAT ----
    gemm(X, sg_W, nullptr, nullptr, p_h, N0);
    k_attn_vec<<<(N0 + 3) / 4, 128>>>(p_h, sg_a, p_es, p_ed, N0);
    k_gat<<<N0, 160>>>(p_rowptr, p_col, nullptr, nullptr, p_h, p_es, p_ed, p_Xstart, N0);

    // pass-invariant pieces of the end-GAT projection:
    //   egc = org_X @ eg_W[320:,:]
    //   FW  = upW1 @ egTop       (fold up-1 GCN proj into end proj)
    //   v1  = upb1 @ egTop
    gemm(p_Xstart, eg_W + 320 * 320, nullptr, nullptr, p_egc, N0);
    gemm(up_W + 320 * 320, eg_W, nullptr, nullptr, p_FW, 320);
    k_vecmat<<<1, DD>>>(up_b + 320, eg_W, p_v1);

    for (int pass = 0; pass < 2; pass++) {
        const float* in0 = (pass == 0) ? p_Xstart : p_Xfin;
        int* gidx1c = (pass == 0) ? p_gidx1f : p_gidx1;
        int* map1c  = (pass == 0) ? p_map1f  : p_map1;
        int* idx1c  = (pass == 0) ? p_idx1f  : p_idxs;
        float* d0 = (pass == 0) ? p_down0 : p_u;
        float* d1 = (pass == 0) ? p_down1 : p_u;

        // down 0 (level 0)
        k_spmm<<<N0, 160>>>(p_rowptr, p_col, nullptr, nullptr, nullptr, in0, p_T, N0);
        gemm(p_T, down_W, down_b, nullptr, d0, N0);

        // R = down0@egTop + v1 + egc  (constant across both passes; down0 is
        // ALWAYS the first-pass tensor per the reference's up-index aliasing)
        if (pass == 0)
            gemm(p_down0, eg_W, p_v1, p_egc, p_R, N0);

        // pool 0 (k=0.8): 6144 -> 4915
        k_scores<<<(N0 + 3) / 4, 128>>>(d0, pool_w, pool_b, 0, p_sc, N0);
        k_sort<<<1, 1024, SORT_N * sizeof(unsigned long long)>>>(p_sc, N0, p_keys, N1);
        k_pool<<<N1, 320>>>(p_keys, p_sc, d0, nullptr, p_v, p_idxs, gidx1c, N1);
        k_seti<<<(N0 + 255) / 256, 256>>>(map1c, -1, N0);
        k_map_set<<<(N1 + 255) / 256, 256>>>(gidx1c, map1c, N1);

        // down 1 (level 1)
        k_spmm<<<N1, 160>>>(p_rowptr, p_col, gidx1c, map1c, nullptr, p_v, p_T, N1);
        gemm(p_T, down_W + 320 * 320, down_b + 320, nullptr, d1, N1);

        // pool 1 (k=0.6): 4915 -> 2949
        k_scores<<<(N1 + 3) / 4, 128>>>(d1, pool_w + 320, pool_b, 1, p_sc, N1);
        k_sort<<<1, 1024, SORT_N * sizeof(unsigned long long)>>>(p_sc, N1, p_keys, N2);
        k_pool<<<N2, 320>>>(p_keys, p_sc, d1, gidx1c, p_v, idx1c, p_gidx2, N2);
        k_seti<<<(N0 + 255) / 256, 256>>>(p_map2, -1, N0);
        k_map_set<<<(N2 + 255) / 256, 256>>>(p_gidx2, p_map2, N2);
        if (pass == 0) {  // inverse of first-pass idx1 (level-1 local -> level-2 local)
            k_seti<<<(N1 + 255) / 256, 256>>>(p_imap1f, -1, N1);
            k_map_set<<<(N2 + 255) / 256, 256>>>(p_idx1f, p_imap1f, N2);
        }

        // bottleneck GAT at level 2
        gemm(p_v, bg_W, nullptr, nullptr, p_h, N2);
        k_attn_vec<<<(N2 + 3) / 4, 128>>>(p_h, bg_a, p_es, p_ed, N2);
        k_gat<<<N2, 160>>>(p_rowptr, p_col, p_gidx2, p_map2, p_h, p_es, p_ed, p_u, N2);

        // up 0: fused unpool via map chain + GCN + first-pass skip
        k_spmm<<<N1, 160>>>(p_rowptr, p_col, p_gidx1f, p_map1f, p_imap1f, p_u, p_T, N1);
        gemm(p_T, up_W, up_b, p_down1, p_u, N1);

        // up 1 + end projection, folded:
        //   h = (T@upW1 + upb1 + down0)@egTop + egc  ==  T@FW + R
        k_spmm<<<N0, 160>>>(p_rowptr, p_col, nullptr, p_map1f, nullptr, p_u, p_T, N0);
        gemm(p_T, p_FW, nullptr, p_R, p_h, N0);

        k_attn_vec<<<(N0 + 3) / 4, 128>>>(p_h, eg_a, p_es, p_ed, N0);
        float* outX = (pass == 0) ? p_Xfin : outp;
        k_gat<<<N0, 160>>>(p_rowptr, p_col, nullptr, nullptr, p_h, p_es, p_ed, outX, N0);
    }

    // fallback copy only if start couldn't be written in place
    if (out_size >= 2 * N0 * DD && p_Xstart != outp + (size_t)N0 * DD)
        k_copyf<<<512, 256>>>(outp + (size_t)N0 * DD, p_Xstart, N0 * DD);
}